// round 1
// baseline (speedup 1.0000x reference)
#include <cuda_runtime.h>
#include <math.h>

// Problem shape (fixed by the dataset): B=4, T=2048, C=1024, fp32.
#define BATCH 4
#define SEQ   2048
#define CH    1024

#define BM 128
#define BN 128
#define BKK 16

// Scratch (allocation-free rule: __device__ globals)
__device__ float g_Q[(long long)BATCH * SEQ * CH]; // 32 MB
__device__ float g_K[(long long)BATCH * SEQ * CH]; // 32 MB
__device__ float g_V[(long long)BATCH * SEQ * CH]; // 32 MB
__device__ float g_S[(long long)BATCH * SEQ * SEQ]; // 64 MB, reused in-place for P

// ---------------------------------------------------------------------------
// NT GEMM: C[m,n] = alpha * sum_k A[m,k] * B[n,k]
// A: [M,K] row-major, B: [N,K] row-major. blockIdx.z batches via strides.
// causal!=0: skip tiles entirely above the diagonal (col0 > row0+BM-1).
// All dims are multiples of the tile sizes (verified for this problem).
// ---------------------------------------------------------------------------
__global__ __launch_bounds__(256) void gemm_nt(
    const float* __restrict__ A, const float* __restrict__ B, float* __restrict__ C,
    int M, int N, int K, float alpha,
    long long sA, long long sB, long long sC, int causal)
{
    A += (long long)blockIdx.z * sA;
    B += (long long)blockIdx.z * sB;
    C += (long long)blockIdx.z * sC;
    const int row0 = blockIdx.y * BM;
    const int col0 = blockIdx.x * BN;
    if (causal && col0 > row0 + (BM - 1)) return;

    __shared__ float As[BKK][BM];
    __shared__ float Bs[BKK][BN];

    const int t  = threadIdx.x;        // 0..255
    const int tx = t & 15;             // 0..15  -> 8 cols each
    const int ty = t >> 4;             // 0..15  -> 8 rows each

    float acc[8][8];
    #pragma unroll
    for (int i = 0; i < 8; i++)
        #pragma unroll
        for (int j = 0; j < 8; j++) acc[i][j] = 0.f;

    // global->shared load mapping (transpose store: smem is [k][m]/[k][n])
    const int lr = t >> 2;             // 0..63 (row within tile; +64 for 2nd)
    const int lk = (t & 3) * 4;        // k offset (float4 along K)

    const float* Ap = A + (long long)(row0 + lr) * K + lk;
    const float* Bp = B + (long long)(col0 + lr) * K + lk;

    for (int k0 = 0; k0 < K; k0 += BKK) {
        float4 a0 = *(const float4*)(Ap + k0);
        float4 a1 = *(const float4*)(Ap + (long long)64 * K + k0);
        float4 b0 = *(const float4*)(Bp + k0);
        float4 b1 = *(const float4*)(Bp + (long long)64 * K + k0);

        As[lk + 0][lr]      = a0.x; As[lk + 1][lr]      = a0.y;
        As[lk + 2][lr]      = a0.z; As[lk + 3][lr]      = a0.w;
        As[lk + 0][lr + 64] = a1.x; As[lk + 1][lr + 64] = a1.y;
        As[lk + 2][lr + 64] = a1.z; As[lk + 3][lr + 64] = a1.w;

        Bs[lk + 0][lr]      = b0.x; Bs[lk + 1][lr]      = b0.y;
        Bs[lk + 2][lr]      = b0.z; Bs[lk + 3][lr]      = b0.w;
        Bs[lk + 0][lr + 64] = b1.x; Bs[lk + 1][lr + 64] = b1.y;
        Bs[lk + 2][lr + 64] = b1.z; Bs[lk + 3][lr + 64] = b1.w;

        __syncthreads();

        #pragma unroll
        for (int k = 0; k < BKK; k++) {
            float a[8], b[8];
            *(float4*)(a)     = *(const float4*)&As[k][ty * 8];
            *(float4*)(a + 4) = *(const float4*)&As[k][ty * 8 + 4];
            *(float4*)(b)     = *(const float4*)&Bs[k][tx * 8];
            *(float4*)(b + 4) = *(const float4*)&Bs[k][tx * 8 + 4];
            #pragma unroll
            for (int i = 0; i < 8; i++)
                #pragma unroll
                for (int j = 0; j < 8; j++)
                    acc[i][j] = fmaf(a[i], b[j], acc[i][j]);
        }
        __syncthreads();
    }

    #pragma unroll
    for (int i = 0; i < 8; i++) {
        long long r = (long long)(row0 + ty * 8 + i) * N + col0 + tx * 8;
        float4 v0 = make_float4(acc[i][0] * alpha, acc[i][1] * alpha,
                                acc[i][2] * alpha, acc[i][3] * alpha);
        float4 v1 = make_float4(acc[i][4] * alpha, acc[i][5] * alpha,
                                acc[i][6] * alpha, acc[i][7] * alpha);
        *(float4*)&C[r]     = v0;
        *(float4*)&C[r + 4] = v1;
    }
}

// ---------------------------------------------------------------------------
// NN GEMM with causal k-bound: C[m,n] = sum_{k<kmax} A[m,k] * B[k,n]
// A = P: [M,K] row-major (zeros above diagonal), B = V: [K,N] row-major.
// kmax = row0 + BM covers all nonzero P entries for this row tile.
// ---------------------------------------------------------------------------
__global__ __launch_bounds__(256) void gemm_nn_causal(
    const float* __restrict__ A, const float* __restrict__ B, float* __restrict__ C,
    int M, int N, int K,
    long long sA, long long sB, long long sC)
{
    A += (long long)blockIdx.z * sA;
    B += (long long)blockIdx.z * sB;
    C += (long long)blockIdx.z * sC;
    const int row0 = blockIdx.y * BM;
    const int col0 = blockIdx.x * BN;
    const int kmax = min(K, row0 + BM);

    __shared__ float As[BKK][BM];
    __shared__ float Bs[BKK][BN];

    const int t  = threadIdx.x;
    const int tx = t & 15;
    const int ty = t >> 4;

    float acc[8][8];
    #pragma unroll
    for (int i = 0; i < 8; i++)
        #pragma unroll
        for (int j = 0; j < 8; j++) acc[i][j] = 0.f;

    const int lr = t >> 2;        // A-tile row 0..63 (+64)
    const int lk = (t & 3) * 4;   // A-tile k offset
    const int br = t >> 5;        // B-tile row 0..7 (+8)
    const int bc = (t & 31) * 4;  // B-tile col offset

    const float* Ap = A + (long long)(row0 + lr) * K + lk;

    for (int k0 = 0; k0 < kmax; k0 += BKK) {
        float4 a0 = *(const float4*)(Ap + k0);
        float4 a1 = *(const float4*)(Ap + (long long)64 * K + k0);
        float4 b0 = *(const float4*)&B[(long long)(k0 + br) * N + col0 + bc];
        float4 b1 = *(const float4*)&B[(long long)(k0 + br + 8) * N + col0 + bc];

        As[lk + 0][lr]      = a0.x; As[lk + 1][lr]      = a0.y;
        As[lk + 2][lr]      = a0.z; As[lk + 3][lr]      = a0.w;
        As[lk + 0][lr + 64] = a1.x; As[lk + 1][lr + 64] = a1.y;
        As[lk + 2][lr + 64] = a1.z; As[lk + 3][lr + 64] = a1.w;

        *(float4*)&Bs[br][bc]     = b0;
        *(float4*)&Bs[br + 8][bc] = b1;

        __syncthreads();

        #pragma unroll
        for (int k = 0; k < BKK; k++) {
            float a[8], b[8];
            *(float4*)(a)     = *(const float4*)&As[k][ty * 8];
            *(float4*)(a + 4) = *(const float4*)&As[k][ty * 8 + 4];
            *(float4*)(b)     = *(const float4*)&Bs[k][tx * 8];
            *(float4*)(b + 4) = *(const float4*)&Bs[k][tx * 8 + 4];
            #pragma unroll
            for (int i = 0; i < 8; i++)
                #pragma unroll
                for (int j = 0; j < 8; j++)
                    acc[i][j] = fmaf(a[i], b[j], acc[i][j]);
        }
        __syncthreads();
    }

    #pragma unroll
    for (int i = 0; i < 8; i++) {
        long long r = (long long)(row0 + ty * 8 + i) * N + col0 + tx * 8;
        *(float4*)&C[r]     = *(float4*)&acc[i][0];
        *(float4*)&C[r + 4] = *(float4*)&acc[i][4];
    }
}

// ---------------------------------------------------------------------------
// Causal row softmax, in place. One block per (q, b) row.
// Reads S[b,q,0..q], writes P[b,q,k] = softmax for k<=q, 0 for k>q.
// ---------------------------------------------------------------------------
__global__ __launch_bounds__(256) void softmax_causal(float* __restrict__ S, int T)
{
    const int q = blockIdx.x;
    float* row = S + ((long long)blockIdx.y * T + q) * (long long)T;

    __shared__ float buf[SEQ];
    __shared__ float red[8];

    const int t = threadIdx.x;
    const int n = q + 1;

    float lmax = -3.0e38f;
    for (int i = t; i < n; i += 256) {
        float v = row[i];
        buf[i] = v;
        lmax = fmaxf(lmax, v);
    }
    #pragma unroll
    for (int o = 16; o; o >>= 1) lmax = fmaxf(lmax, __shfl_xor_sync(0xFFFFFFFFu, lmax, o));
    if ((t & 31) == 0) red[t >> 5] = lmax;
    __syncthreads();
    if (t < 32) {
        float v = (t < 8) ? red[t] : -3.0e38f;
        #pragma unroll
        for (int o = 4; o; o >>= 1) v = fmaxf(v, __shfl_xor_sync(0xFFFFFFFFu, v, o));
        if (t == 0) red[0] = v;
    }
    __syncthreads();
    const float gmax = red[0];

    float lsum = 0.f;
    for (int i = t; i < n; i += 256) {
        float e = expf(buf[i] - gmax);
        buf[i] = e;
        lsum += e;
    }
    __syncthreads();  // everyone has read red[0]; safe to reuse
    #pragma unroll
    for (int o = 16; o; o >>= 1) lsum += __shfl_xor_sync(0xFFFFFFFFu, lsum, o);
    if ((t & 31) == 0) red[t >> 5] = lsum;
    __syncthreads();
    if (t < 32) {
        float v = (t < 8) ? red[t] : 0.f;
        #pragma unroll
        for (int o = 4; o; o >>= 1) v += __shfl_xor_sync(0xFFFFFFFFu, v, o);
        if (t == 0) red[0] = v;
    }
    __syncthreads();
    const float inv = 1.f / red[0];

    for (int i = t; i < T; i += 256)
        row[i] = (i < n) ? buf[i] * inv : 0.f;
}

// ---------------------------------------------------------------------------
extern "C" void kernel_launch(void* const* d_in, const int* in_sizes, int n_in,
                              void* d_out, int out_size)
{
    (void)in_sizes; (void)n_in; (void)out_size;
    const float* x  = (const float*)d_in[0];
    const float* Wq = (const float*)d_in[1];
    const float* Wk = (const float*)d_in[2];
    const float* Wv = (const float*)d_in[3];
    float* out = (float*)d_out;

    float *q, *k, *v, *s;
    cudaGetSymbolAddress((void**)&q, g_Q);
    cudaGetSymbolAddress((void**)&k, g_K);
    cudaGetSymbolAddress((void**)&v, g_V);
    cudaGetSymbolAddress((void**)&s, g_S);

    const int  M  = BATCH * SEQ;       // 8192
    const long long qkStride = (long long)SEQ * CH;   // per-batch Q/K/V stride
    const long long sStride  = (long long)SEQ * SEQ;  // per-batch S stride
    const float scale = 1.0f / 32.0f;  // C^-0.5, C=1024

    dim3 blk(256);

    // 1) QKV projections: [8192,1024] = x @ W^T  (NT)
    dim3 g1(CH / BN, M / BM, 1);
    gemm_nt<<<g1, blk>>>(x, Wq, q, M, CH, CH, 1.f, 0, 0, 0, 0);
    gemm_nt<<<g1, blk>>>(x, Wk, k, M, CH, CH, 1.f, 0, 0, 0, 0);
    gemm_nt<<<g1, blk>>>(x, Wv, v, M, CH, CH, 1.f, 0, 0, 0, 0);

    // 2) S = scale * Q @ K^T per batch (NT, causal tile skip)
    dim3 g2(SEQ / BN, SEQ / BM, BATCH);
    gemm_nt<<<g2, blk>>>(q, k, s, SEQ, SEQ, CH, scale, qkStride, qkStride, sStride, 1);

    // 3) causal softmax in place (S -> P)
    softmax_causal<<<dim3(SEQ, BATCH), 256>>>(s, SEQ);

    // 4) out = P @ V per batch (NN, causal k-bound)
    dim3 g3(CH / BN, SEQ / BM, BATCH);
    gemm_nn_causal<<<g3, blk>>>(s, v, out, SEQ, CH, SEQ, sStride, qkStride, qkStride);
}

// round 4
// speedup vs baseline: 2.5588x; 2.5588x over previous
#include <cuda_runtime.h>
#include <cuda_bf16.h>
#include <cstdint>

// Shape fixed by dataset: B=4, T=2048, C=1024, fp32 in/out.
#define BATCH 4
#define SEQ   2048
#define CH    1024

#define TM 128
#define TN 128
#define BK 64          // K elements per chunk (bf16) = 128B rows
#define STAGES 3

#define STG_A_H 0
#define STG_A_L 16384
#define STG_B_H 32768
#define STG_B_L 49152
#define STG_BYTES 65536
#define SMEM_BYTES (STAGES * STG_BYTES)
#define TRP 132        // transpose buffer row pitch (floats)

// ---------------- scratch (__device__ globals; no allocs allowed) -------------
__device__ __nv_bfloat16 g_xh[(size_t)BATCH*SEQ*CH], g_xl[(size_t)BATCH*SEQ*CH];
__device__ __nv_bfloat16 g_wqh[CH*CH], g_wql[CH*CH];
__device__ __nv_bfloat16 g_wkh[CH*CH], g_wkl[CH*CH];
__device__ __nv_bfloat16 g_wvh[CH*CH], g_wvl[CH*CH];
__device__ __nv_bfloat16 g_qh[(size_t)BATCH*SEQ*CH], g_ql[(size_t)BATCH*SEQ*CH];
__device__ __nv_bfloat16 g_kh[(size_t)BATCH*SEQ*CH], g_kl[(size_t)BATCH*SEQ*CH];
__device__ __nv_bfloat16 g_vth[(size_t)BATCH*CH*SEQ], g_vtl[(size_t)BATCH*CH*SEQ]; // V^T [b][c][t]
__device__ float         g_S [(size_t)BATCH*SEQ*SEQ];
__device__ __nv_bfloat16 g_ph[(size_t)BATCH*SEQ*SEQ], g_pl[(size_t)BATCH*SEQ*SEQ];

// ---------------- helpers ----------------
__device__ __forceinline__ uint32_t smem_u32(const void* p){
    uint32_t a;
    asm("{ .reg .u64 t; cvta.to.shared.u64 t, %1; cvt.u32.u64 %0, t; }" : "=r"(a) : "l"(p));
    return a;
}
__device__ __forceinline__ void split1(float v, __nv_bfloat16& h, __nv_bfloat16& l){
    h = __float2bfloat16_rn(v);
    l = __float2bfloat16_rn(v - __bfloat162float(h));
}
__device__ __forceinline__ uint32_t pack2(__nv_bfloat16 a, __nv_bfloat16 b){
    __nv_bfloat162 p = __halves2bfloat162(a, b);
    return *(uint32_t*)&p;
}
__device__ __forceinline__ void ldsm4(uint32_t* r, uint32_t a){
    asm volatile("ldmatrix.sync.aligned.m8n8.x4.shared.b16 {%0,%1,%2,%3}, [%4];"
        : "=r"(r[0]),"=r"(r[1]),"=r"(r[2]),"=r"(r[3]) : "r"(a));
}
__device__ __forceinline__ void ldsm2(uint32_t* r, uint32_t a){
    asm volatile("ldmatrix.sync.aligned.m8n8.x2.shared.b16 {%0,%1}, [%2];"
        : "=r"(r[0]),"=r"(r[1]) : "r"(a));
}
__device__ __forceinline__ void mma16816(float* c, const uint32_t* a, const uint32_t* b){
    asm volatile(
        "mma.sync.aligned.m16n8k16.row.col.f32.bf16.bf16.f32 "
        "{%0,%1,%2,%3}, {%4,%5,%6,%7}, {%8,%9}, {%0,%1,%2,%3};"
        : "+f"(c[0]), "+f"(c[1]), "+f"(c[2]), "+f"(c[3])
        : "r"(a[0]), "r"(a[1]), "r"(a[2]), "r"(a[3]), "r"(b[0]), "r"(b[1]));
}
#define CPA16(dst, src) \
    asm volatile("cp.async.cg.shared.global [%0], [%1], 16;" :: "r"(dst), "l"(src))
#define CP_COMMIT() asm volatile("cp.async.commit_group;" ::: "memory")
#define CP_WAIT1()  asm volatile("cp.async.wait_group 1;" ::: "memory")

// ---------------------------------------------------------------------------
// split fp32 -> (hi, lo) bf16
// ---------------------------------------------------------------------------
__global__ __launch_bounds__(256) void split_k(
    const float4* __restrict__ in, uint2* __restrict__ oh, uint2* __restrict__ ol, int n4)
{
    int i = blockIdx.x * 256 + threadIdx.x;
    if (i >= n4) return;
    float4 v = in[i];
    __nv_bfloat16 h0,h1,h2,h3,l0,l1,l2,l3;
    split1(v.x,h0,l0); split1(v.y,h1,l1); split1(v.z,h2,l2); split1(v.w,h3,l3);
    uint2 H, L;
    H.x = pack2(h0,h1); H.y = pack2(h2,h3);
    L.x = pack2(l0,l1); L.y = pack2(l2,l3);
    oh[i] = H; ol[i] = L;
}

// ---------------------------------------------------------------------------
// NT GEMM, bf16 3-split on tensor cores:
//   C[m,n] = alpha * sum_k (Ah+Al)[m,k]*(Bh+Bl)[n,k]   (ll term dropped)
// mode 0: C fp32.  mode 1: split bf16 -> (Ch, Cl).  mode 2: transposed split
//   bf16 -> Vt layout [b][c][t] (batch derived from global row).
// causal: skip tiles with col0 > row0+TM-1.  kbound: K clipped to row0+TM.
// ---------------------------------------------------------------------------
__global__ __launch_bounds__(256, 1) void gemm_bf3(
    const __nv_bfloat16* __restrict__ Ah, const __nv_bfloat16* __restrict__ Al,
    const __nv_bfloat16* __restrict__ Bh, const __nv_bfloat16* __restrict__ Bl,
    float* __restrict__ C, __nv_bfloat16* __restrict__ Ch, __nv_bfloat16* __restrict__ Cl,
    int K, int lda, int ldb, int ldc, float alpha,
    long long sA, long long sB, long long sC,
    int causal, int kbound, int mode)
{
    const int row0 = blockIdx.y * TM;
    const int col0 = blockIdx.x * TN;
    if (causal && col0 > row0 + (TM - 1)) return;

    const long long zo = blockIdx.z;
    Ah += zo * sA; Al += zo * sA;
    Bh += zo * sB; Bl += zo * sB;

    const int kend = kbound ? min(K, row0 + TM) : K;
    const int nch  = kend / BK;

    extern __shared__ char sm[];
    const uint32_t smu = smem_u32(sm);

    const int t = threadIdx.x;

    // ---- producer mapping: 2 threads/row, 4x16B per thread per tile ----
    const int prow  = t >> 1;
    const int phalf = t & 1;
    const uint32_t pdst = (uint32_t)(prow * 128 + phalf * 64);
    const uint32_t pswz = (uint32_t)((prow & 7) << 4);
    const __nv_bfloat16* gAh = Ah + (long long)(row0 + prow) * lda + phalf * 32;
    const __nv_bfloat16* gAl = Al + (long long)(row0 + prow) * lda + phalf * 32;
    const __nv_bfloat16* gBh = Bh + (long long)(col0 + prow) * ldb + phalf * 32;
    const __nv_bfloat16* gBl = Bl + (long long)(col0 + prow) * ldb + phalf * 32;

    #define LOAD_CHUNK(s, i) do {                                              \
        uint32_t base = smu + (uint32_t)(s) * STG_BYTES;                       \
        int kk0 = (i) * BK;                                                    \
        _Pragma("unroll")                                                      \
        for (int u = 0; u < 4; u++) {                                          \
            uint32_t d = (pdst + u * 16) ^ pswz;                               \
            CPA16(base + STG_A_H + d, gAh + kk0 + u * 8);                      \
            CPA16(base + STG_A_L + d, gAl + kk0 + u * 8);                      \
            CPA16(base + STG_B_H + d, gBh + kk0 + u * 8);                      \
            CPA16(base + STG_B_L + d, gBl + kk0 + u * 8);                      \
        }                                                                      \
        CP_COMMIT();                                                           \
    } while (0)

    // ---- consumer mapping ----
    const int wid  = t >> 5;
    const int lane = t & 31;
    const int m0 = (wid >> 2) * 64;   // 2 warp rows
    const int n0 = (wid & 3) * 32;    // 4 warp cols

    const int t4  = lane >> 3;
    const int rr  = lane & 7;
    const uint32_t abase = (uint32_t)((m0 + rr + (t4 & 1) * 8) * 128 + (t4 >> 1) * 16);
    const uint32_t axor  = (uint32_t)(rr << 4);
    const int l16 = lane & 15;
    const uint32_t bbase = (uint32_t)((n0 + (l16 & 7)) * 128 + (l16 >> 3) * 16);
    const uint32_t bxor  = (uint32_t)((l16 & 7) << 4);

    float acc[4][4][4];
    #pragma unroll
    for (int mi = 0; mi < 4; mi++)
        #pragma unroll
        for (int ni = 0; ni < 4; ni++)
            #pragma unroll
            for (int r = 0; r < 4; r++) acc[mi][ni][r] = 0.f;

    int fetch = 0;
    #pragma unroll
    for (int s = 0; s < STAGES - 1; s++) {
        if (fetch < nch) { LOAD_CHUNK(fetch % STAGES, fetch); fetch++; }
        else CP_COMMIT();
    }

    for (int i = 0; i < nch; i++) {
        CP_WAIT1();
        __syncthreads();

        const uint32_t sb = smu + (uint32_t)(i % STAGES) * STG_BYTES;
        #pragma unroll
        for (int ks = 0; ks < 4; ks++) {
            uint32_t ah[4][4], al[4][4], bh[4][2], bl[4][2];
            #pragma unroll
            for (int mi = 0; mi < 4; mi++) {
                uint32_t o = (abase + mi * 2048 + ks * 32) ^ axor;
                ldsm4(ah[mi], sb + STG_A_H + o);
                ldsm4(al[mi], sb + STG_A_L + o);
            }
            #pragma unroll
            for (int ni = 0; ni < 4; ni++) {
                uint32_t o = (bbase + ni * 1024 + ks * 32) ^ bxor;
                ldsm2(bh[ni], sb + STG_B_H + o);
                ldsm2(bl[ni], sb + STG_B_L + o);
            }
            #pragma unroll
            for (int mi = 0; mi < 4; mi++)
                #pragma unroll
                for (int ni = 0; ni < 4; ni++) {
                    mma16816(acc[mi][ni], ah[mi], bh[ni]);
                    mma16816(acc[mi][ni], al[mi], bh[ni]);
                    mma16816(acc[mi][ni], ah[mi], bl[ni]);
                }
        }

        if (fetch < nch) { LOAD_CHUNK(fetch % STAGES, fetch); fetch++; }
        else CP_COMMIT();
    }

    // -------- epilogue --------
    const int er = lane >> 2;          // 0..7
    const int ec = (lane & 3) * 2;     // 0,2,4,6

    if (mode == 0) {
        float* Cp = C + zo * sC;
        #pragma unroll
        for (int mi = 0; mi < 4; mi++)
            #pragma unroll
            for (int ni = 0; ni < 4; ni++) {
                int r = row0 + m0 + mi * 16 + er;
                int c = col0 + n0 + ni * 8 + ec;
                float2 v0 = make_float2(acc[mi][ni][0] * alpha, acc[mi][ni][1] * alpha);
                float2 v1 = make_float2(acc[mi][ni][2] * alpha, acc[mi][ni][3] * alpha);
                *(float2*)&Cp[(long long)r * ldc + c]       = v0;
                *(float2*)&Cp[(long long)(r + 8) * ldc + c] = v1;
            }
    } else if (mode == 1) {
        #pragma unroll
        for (int mi = 0; mi < 4; mi++)
            #pragma unroll
            for (int ni = 0; ni < 4; ni++) {
                int r = row0 + m0 + mi * 16 + er;
                int c = col0 + n0 + ni * 8 + ec;
                __nv_bfloat16 h0,h1,h2,h3,l0,l1,l2,l3;
                split1(acc[mi][ni][0] * alpha, h0, l0);
                split1(acc[mi][ni][1] * alpha, h1, l1);
                split1(acc[mi][ni][2] * alpha, h2, l2);
                split1(acc[mi][ni][3] * alpha, h3, l3);
                *(uint32_t*)&Ch[(long long)r * ldc + c]       = pack2(h0, h1);
                *(uint32_t*)&Cl[(long long)r * ldc + c]       = pack2(l0, l1);
                *(uint32_t*)&Ch[(long long)(r + 8) * ldc + c] = pack2(h2, h3);
                *(uint32_t*)&Cl[(long long)(r + 8) * ldc + c] = pack2(l2, l3);
            }
    } else {
        // transposed split store via smem (Vt[b][c][t])
        __syncthreads();
        float* Tr = (float*)sm;
        #pragma unroll
        for (int mi = 0; mi < 4; mi++)
            #pragma unroll
            for (int ni = 0; ni < 4; ni++) {
                int m = m0 + mi * 16 + er;
                int c = n0 + ni * 8 + ec;
                Tr[c * TRP + m]           = acc[mi][ni][0] * alpha;
                Tr[(c + 1) * TRP + m]     = acc[mi][ni][1] * alpha;
                Tr[c * TRP + m + 8]       = acc[mi][ni][2] * alpha;
                Tr[(c + 1) * TRP + m + 8] = acc[mi][ni][3] * alpha;
            }
        __syncthreads();
        const int b   = row0 >> 11;
        const int tt0 = row0 & (SEQ - 1);
        const int cc  = t >> 1;
        const int seg = (t & 1) * 64;
        long long off = ((long long)b * CH + col0 + cc) * SEQ + tt0 + seg;
        #pragma unroll
        for (int j = 0; j < 16; j++) {
            float4 v = *(float4*)&Tr[cc * TRP + seg + j * 4];
            __nv_bfloat16 h0,h1,h2,h3,l0,l1,l2,l3;
            split1(v.x,h0,l0); split1(v.y,h1,l1); split1(v.z,h2,l2); split1(v.w,h3,l3);
            uint2 H, L;
            H.x = pack2(h0,h1); H.y = pack2(h2,h3);
            L.x = pack2(l0,l1); L.y = pack2(l2,l3);
            *(uint2*)&Ch[off + j * 4] = H;
            *(uint2*)&Cl[off + j * 4] = L;
        }
    }
}

// ---------------------------------------------------------------------------
// Causal row softmax: S fp32 -> split bf16 P (hi, lo). Zero fill to kmax.
// ---------------------------------------------------------------------------
__global__ __launch_bounds__(256) void softmax_split(
    const float* __restrict__ S, __nv_bfloat16* __restrict__ Ph,
    __nv_bfloat16* __restrict__ Pl, int T)
{
    const int q = blockIdx.x;
    const long long off = ((long long)blockIdx.y * T + q) * (long long)T;
    const float* row = S + off;

    __shared__ float buf[SEQ];
    __shared__ float red[8];

    const int t = threadIdx.x;
    const int n = q + 1;
    const int kmax = (q & ~(TM - 1)) + TM;

    float lmax = -3.0e38f;
    for (int i = t; i < n; i += 256) {
        float v = row[i];
        buf[i] = v;
        lmax = fmaxf(lmax, v);
    }
    #pragma unroll
    for (int o = 16; o; o >>= 1) lmax = fmaxf(lmax, __shfl_xor_sync(0xFFFFFFFFu, lmax, o));
    if ((t & 31) == 0) red[t >> 5] = lmax;
    __syncthreads();
    if (t < 32) {
        float v = (t < 8) ? red[t] : -3.0e38f;
        #pragma unroll
        for (int o = 4; o; o >>= 1) v = fmaxf(v, __shfl_xor_sync(0xFFFFFFFFu, v, o));
        if (t == 0) red[0] = v;
    }
    __syncthreads();
    const float gmax = red[0];

    float lsum = 0.f;
    for (int i = t; i < n; i += 256) {
        float e = expf(buf[i] - gmax);
        buf[i] = e;
        lsum += e;
    }
    __syncthreads();
    #pragma unroll
    for (int o = 16; o; o >>= 1) lsum += __shfl_xor_sync(0xFFFFFFFFu, lsum, o);
    if ((t & 31) == 0) red[t >> 5] = lsum;
    __syncthreads();
    if (t < 32) {
        float v = (t < 8) ? red[t] : 0.f;
        #pragma unroll
        for (int o = 4; o; o >>= 1) v += __shfl_xor_sync(0xFFFFFFFFu, v, o);
        if (t == 0) red[0] = v;
    }
    __syncthreads();
    const float inv = 1.f / red[0];

    for (int i = t; i < kmax; i += 256) {
        float v = (i < n) ? buf[i] * inv : 0.f;
        __nv_bfloat16 h, l;
        split1(v, h, l);
        Ph[off + i] = h;
        Pl[off + i] = l;
    }
}

// ---------------------------------------------------------------------------
extern "C" void kernel_launch(void* const* d_in, const int* in_sizes, int n_in,
                              void* d_out, int out_size)
{
    (void)in_sizes; (void)n_in; (void)out_size;
    const float* x  = (const float*)d_in[0];
    const float* Wq = (const float*)d_in[1];
    const float* Wk = (const float*)d_in[2];
    const float* Wv = (const float*)d_in[3];
    float* out = (float*)d_out;

    __nv_bfloat16 *xh,*xl,*wqh,*wql,*wkh,*wkl,*wvh,*wvl,*qh,*ql,*kh,*kl,*vth,*vtl,*ph,*pl;
    float* s;
    cudaGetSymbolAddress((void**)&xh,  g_xh);  cudaGetSymbolAddress((void**)&xl,  g_xl);
    cudaGetSymbolAddress((void**)&wqh, g_wqh); cudaGetSymbolAddress((void**)&wql, g_wql);
    cudaGetSymbolAddress((void**)&wkh, g_wkh); cudaGetSymbolAddress((void**)&wkl, g_wkl);
    cudaGetSymbolAddress((void**)&wvh, g_wvh); cudaGetSymbolAddress((void**)&wvl, g_wvl);
    cudaGetSymbolAddress((void**)&qh,  g_qh);  cudaGetSymbolAddress((void**)&ql,  g_ql);
    cudaGetSymbolAddress((void**)&kh,  g_kh);  cudaGetSymbolAddress((void**)&kl,  g_kl);
    cudaGetSymbolAddress((void**)&vth, g_vth); cudaGetSymbolAddress((void**)&vtl, g_vtl);
    cudaGetSymbolAddress((void**)&ph,  g_ph);  cudaGetSymbolAddress((void**)&pl,  g_pl);
    cudaGetSymbolAddress((void**)&s,   g_S);

    cudaFuncSetAttribute(gemm_bf3, cudaFuncAttributeMaxDynamicSharedMemorySize, SMEM_BYTES);

    const int M = BATCH * SEQ;                          // 8192
    const long long qkS = (long long)SEQ * CH;
    const long long vtS = (long long)CH * SEQ;
    const long long sS  = (long long)SEQ * SEQ;
    const float scale = 1.0f / 32.0f;

    // 0) split inputs to bf16 hi/lo
    split_k<<<(M * CH / 4) / 256, 256>>>((const float4*)x, (uint2*)xh, (uint2*)xl, M * CH / 4);
    split_k<<<(CH * CH / 4) / 256, 256>>>((const float4*)Wq, (uint2*)wqh, (uint2*)wql, CH * CH / 4);
    split_k<<<(CH * CH / 4) / 256, 256>>>((const float4*)Wk, (uint2*)wkh, (uint2*)wkl, CH * CH / 4);
    split_k<<<(CH * CH / 4) / 256, 256>>>((const float4*)Wv, (uint2*)wvh, (uint2*)wvl, CH * CH / 4);

    dim3 blk(256);

    // 1) QKV projections (NT). Q pre-scaled; Q/K split; V transposed+split.
    dim3 g1(CH / TN, M / TM, 1);
    gemm_bf3<<<g1, blk, SMEM_BYTES>>>(xh, xl, wqh, wql, nullptr, qh, ql,
                                      CH, CH, CH, CH, scale, 0, 0, 0, 0, 0, 1);
    gemm_bf3<<<g1, blk, SMEM_BYTES>>>(xh, xl, wkh, wkl, nullptr, kh, kl,
                                      CH, CH, CH, CH, 1.f, 0, 0, 0, 0, 0, 1);
    gemm_bf3<<<g1, blk, SMEM_BYTES>>>(xh, xl, wvh, wvl, nullptr, vth, vtl,
                                      CH, CH, CH, CH, 1.f, 0, 0, 0, 0, 0, 2);

    // 2) S = (Q*scale) @ K^T per batch (causal tile skip)
    dim3 g2(SEQ / TN, SEQ / TM, BATCH);
    gemm_bf3<<<g2, blk, SMEM_BYTES>>>(qh, ql, kh, kl, s, nullptr, nullptr,
                                      CH, CH, CH, SEQ, 1.f, qkS, qkS, sS, 1, 0, 0);

    // 3) softmax -> split P
    softmax_split<<<dim3(SEQ, BATCH), 256>>>(s, ph, pl, SEQ);

    // 4) out = P @ V = P @ (V^T)^T per batch (NT against Vt, causal k-bound)
    dim3 g3(CH / TN, SEQ / TM, BATCH);
    gemm_bf3<<<g3, blk, SMEM_BYTES>>>(ph, pl, vth, vtl, out, nullptr, nullptr,
                                      SEQ, SEQ, SEQ, CH, 1.f, sS, vtS, qkS, 0, 1, 0);
}

// round 5
// speedup vs baseline: 3.0719x; 1.2005x over previous
#include <cuda_runtime.h>
#include <cuda_bf16.h>
#include <cstdint>

// Shape fixed by dataset: B=4, T=2048, C=1024, fp32 in/out.
#define BATCH 4
#define SEQ   2048
#define CH    1024

#define TM 128
#define TN 256
#define BK 32          // K elems per chunk (bf16) = 64B rows
#define STAGES 4

#define STG_A_H 0
#define STG_A_L 8192
#define STG_B_H 16384
#define STG_B_L 32768
#define STG_BYTES 49152
#define SMEM_BYTES (STAGES * STG_BYTES)   // 192 KB

#define SWZ64(o) ((o) ^ ((((unsigned)(o)) >> 3) & 0x30u))

// ---------------- scratch (__device__ globals; no allocs allowed) -------------
__device__ __nv_bfloat16 g_xh[(size_t)BATCH*SEQ*CH], g_xl[(size_t)BATCH*SEQ*CH];
__device__ __nv_bfloat16 g_wqh[CH*CH], g_wql[CH*CH];
__device__ __nv_bfloat16 g_wkh[CH*CH], g_wkl[CH*CH];
__device__ __nv_bfloat16 g_wvh[CH*CH], g_wvl[CH*CH];
__device__ __nv_bfloat16 g_qh[(size_t)BATCH*SEQ*CH], g_ql[(size_t)BATCH*SEQ*CH];
__device__ __nv_bfloat16 g_kh[(size_t)BATCH*SEQ*CH], g_kl[(size_t)BATCH*SEQ*CH];
__device__ __nv_bfloat16 g_vth[(size_t)BATCH*CH*SEQ], g_vtl[(size_t)BATCH*CH*SEQ]; // V^T [b][c][t]
__device__ float         g_S [(size_t)BATCH*SEQ*SEQ];
__device__ __nv_bfloat16 g_ph[(size_t)BATCH*SEQ*SEQ], g_pl[(size_t)BATCH*SEQ*SEQ];

// ---------------- helpers ----------------
__device__ __forceinline__ uint32_t smem_u32(const void* p){
    uint32_t a;
    asm("{ .reg .u64 t; cvta.to.shared.u64 t, %1; cvt.u32.u64 %0, t; }" : "=r"(a) : "l"(p));
    return a;
}
__device__ __forceinline__ void split1(float v, __nv_bfloat16& h, __nv_bfloat16& l){
    h = __float2bfloat16_rn(v);
    l = __float2bfloat16_rn(v - __bfloat162float(h));
}
__device__ __forceinline__ uint32_t pack2(__nv_bfloat16 a, __nv_bfloat16 b){
    __nv_bfloat162 p = __halves2bfloat162(a, b);
    return *(uint32_t*)&p;
}
__device__ __forceinline__ void ldsm4(uint32_t* r, uint32_t a){
    asm volatile("ldmatrix.sync.aligned.m8n8.x4.shared.b16 {%0,%1,%2,%3}, [%4];"
        : "=r"(r[0]),"=r"(r[1]),"=r"(r[2]),"=r"(r[3]) : "r"(a));
}
__device__ __forceinline__ void mma16816(float* c, const uint32_t* a, const uint32_t* b){
    asm volatile(
        "mma.sync.aligned.m16n8k16.row.col.f32.bf16.bf16.f32 "
        "{%0,%1,%2,%3}, {%4,%5,%6,%7}, {%8,%9}, {%0,%1,%2,%3};"
        : "+f"(c[0]), "+f"(c[1]), "+f"(c[2]), "+f"(c[3])
        : "r"(a[0]), "r"(a[1]), "r"(a[2]), "r"(a[3]), "r"(b[0]), "r"(b[1]));
}
#define CPA16(dst, src) \
    asm volatile("cp.async.cg.shared.global [%0], [%1], 16;" :: "r"(dst), "l"(src))
#define CP_COMMIT() asm volatile("cp.async.commit_group;" ::: "memory")
#define CP_WAIT2()  asm volatile("cp.async.wait_group 2;" ::: "memory")

// ---------------------------------------------------------------------------
// split fp32 -> (hi, lo) bf16
// ---------------------------------------------------------------------------
__global__ __launch_bounds__(256) void split_k(
    const float4* __restrict__ in, uint2* __restrict__ oh, uint2* __restrict__ ol, int n4)
{
    int i = blockIdx.x * 256 + threadIdx.x;
    if (i >= n4) return;
    float4 v = in[i];
    __nv_bfloat16 h0,h1,h2,h3,l0,l1,l2,l3;
    split1(v.x,h0,l0); split1(v.y,h1,l1); split1(v.z,h2,l2); split1(v.w,h3,l3);
    uint2 H, L;
    H.x = pack2(h0,h1); H.y = pack2(h2,h3);
    L.x = pack2(l0,l1); L.y = pack2(l2,l3);
    oh[i] = H; ol[i] = L;
}

// ---------------------------------------------------------------------------
// NT GEMM, bf16 3-split on tensor cores, 128x256 tile, 512 threads:
//   C[m,n] = alpha * sum_k (Ah+Al)[m,k]*(Bh+Bl)[n,k]   (ll term dropped)
// mode 0: C fp32.  mode 1: split bf16 -> (Ch, Cl).
// causal: skip tiles with col0 > row0+TM-1.  kbound: K clipped to row0+TM.
// ---------------------------------------------------------------------------
__global__ __launch_bounds__(512, 1) void gemm_bf3(
    const __nv_bfloat16* __restrict__ Ah, const __nv_bfloat16* __restrict__ Al,
    const __nv_bfloat16* __restrict__ Bh, const __nv_bfloat16* __restrict__ Bl,
    float* __restrict__ C, __nv_bfloat16* __restrict__ Ch, __nv_bfloat16* __restrict__ Cl,
    int K, int lda, int ldb, int ldc, float alpha,
    long long sA, long long sB, long long sC,
    int causal, int kbound, int mode)
{
    const int row0 = blockIdx.y * TM;
    const int col0 = blockIdx.x * TN;
    if (causal && col0 > row0 + (TM - 1)) return;

    const long long zo = blockIdx.z;
    Ah += zo * sA; Al += zo * sA;
    Bh += zo * sB; Bl += zo * sB;

    const int kend = kbound ? min(K, row0 + TM) : K;
    const int nch  = kend / BK;

    extern __shared__ char sm[];
    const uint32_t smu = smem_u32(sm);

    const int t = threadIdx.x;

    // ---- producer mapping: 1x16B per thread per 8KB region ----
    const int prow = t >> 2;               // 0..127
    const int pch  = t & 3;                // 16B chunk within 64B row
    const uint32_t dA = SWZ64((uint32_t)(prow * 64 + pch * 16));
    const __nv_bfloat16* gAh  = Ah + (long long)(row0 + prow) * lda + pch * 8;
    const __nv_bfloat16* gAl  = Al + (long long)(row0 + prow) * lda + pch * 8;
    const __nv_bfloat16* gBh0 = Bh + (long long)(col0 + prow) * ldb + pch * 8;
    const __nv_bfloat16* gBh1 = Bh + (long long)(col0 + prow + 128) * ldb + pch * 8;
    const __nv_bfloat16* gBl0 = Bl + (long long)(col0 + prow) * ldb + pch * 8;
    const __nv_bfloat16* gBl1 = Bl + (long long)(col0 + prow + 128) * ldb + pch * 8;

    #define LOAD_CHUNK(s, i) do {                                              \
        uint32_t base = smu + (uint32_t)(s) * STG_BYTES;                       \
        long long kk0 = (long long)(i) * BK;                                   \
        CPA16(base + STG_A_H + dA,        gAh  + kk0);                         \
        CPA16(base + STG_A_L + dA,        gAl  + kk0);                         \
        CPA16(base + STG_B_H + dA,        gBh0 + kk0);                         \
        CPA16(base + STG_B_H + dA + 8192, gBh1 + kk0);                         \
        CPA16(base + STG_B_L + dA,        gBl0 + kk0);                         \
        CPA16(base + STG_B_L + dA + 8192, gBl1 + kk0);                         \
        CP_COMMIT();                                                           \
    } while (0)

    // ---- consumer mapping: 16 warps, warp tile 32x64 (4x4 warp grid) ----
    const int wid  = t >> 5;
    const int lane = t & 31;
    const int m0 = (wid >> 2) * 32;
    const int n0 = (wid & 3) * 64;

    const int rr = lane & 7;
    const int t4 = lane >> 3;
    // A: x4 ldsm -> 16x16 tile (rows m, k16)
    const int arow = m0 + rr + (t4 & 1) * 8;
    const uint32_t a_base = (uint32_t)(arow * 64 + (t4 >> 1) * 16);
    const uint32_t aswz   = (uint32_t)(((arow >> 1) & 3) << 4);
    // B: x4 ldsm -> two n8k16 fragments (rows n..n+15)
    const int brow = n0 + rr + (t4 >> 1) * 8;
    const uint32_t b_base = (uint32_t)(brow * 64 + (t4 & 1) * 16);
    const uint32_t bswz   = (uint32_t)(((brow >> 1) & 3) << 4);

    float acc[2][8][4];
    #pragma unroll
    for (int mi = 0; mi < 2; mi++)
        #pragma unroll
        for (int ni = 0; ni < 8; ni++)
            #pragma unroll
            for (int r = 0; r < 4; r++) acc[mi][ni][r] = 0.f;

    int fetch = 0;
    #pragma unroll
    for (int s = 0; s < STAGES - 1; s++) {
        if (fetch < nch) { LOAD_CHUNK(fetch % STAGES, fetch); fetch++; }
        else CP_COMMIT();
    }

    for (int i = 0; i < nch; i++) {
        CP_WAIT2();
        __syncthreads();

        if (fetch < nch) { LOAD_CHUNK(fetch % STAGES, fetch); fetch++; }
        else CP_COMMIT();

        const uint32_t sb = smu + (uint32_t)(i % STAGES) * STG_BYTES;
        #pragma unroll
        for (int ks = 0; ks < 2; ks++) {
            uint32_t ah[2][4], al[2][4];
            #pragma unroll
            for (int mi = 0; mi < 2; mi++) {
                uint32_t o = (a_base + mi * 1024 + ks * 32) ^ aswz;
                ldsm4(ah[mi], sb + STG_A_H + o);
                ldsm4(al[mi], sb + STG_A_L + o);
            }
            #pragma unroll
            for (int half = 0; half < 2; half++) {
                uint32_t bh[2][4], bl[2][4];
                #pragma unroll
                for (int p = 0; p < 2; p++) {
                    uint32_t o = (b_base + (half * 2 + p) * 1024 + ks * 32) ^ bswz;
                    ldsm4(bh[p], sb + STG_B_H + o);
                    ldsm4(bl[p], sb + STG_B_L + o);
                }
                #pragma unroll
                for (int mi = 0; mi < 2; mi++)
                    #pragma unroll
                    for (int p = 0; p < 2; p++)
                        #pragma unroll
                        for (int sub = 0; sub < 2; sub++) {
                            int ni = half * 4 + p * 2 + sub;
                            mma16816(acc[mi][ni], ah[mi], bh[p] + 2 * sub);
                            mma16816(acc[mi][ni], al[mi], bh[p] + 2 * sub);
                            mma16816(acc[mi][ni], ah[mi], bl[p] + 2 * sub);
                        }
            }
        }
    }

    // -------- epilogue --------
    const int er = lane >> 2;
    const int ec = (lane & 3) * 2;

    if (mode == 0) {
        float* Cp = C + zo * sC;
        #pragma unroll
        for (int mi = 0; mi < 2; mi++)
            #pragma unroll
            for (int ni = 0; ni < 8; ni++) {
                int r = row0 + m0 + mi * 16 + er;
                int c = col0 + n0 + ni * 8 + ec;
                float2 v0 = make_float2(acc[mi][ni][0] * alpha, acc[mi][ni][1] * alpha);
                float2 v1 = make_float2(acc[mi][ni][2] * alpha, acc[mi][ni][3] * alpha);
                *(float2*)&Cp[(long long)r * ldc + c]       = v0;
                *(float2*)&Cp[(long long)(r + 8) * ldc + c] = v1;
            }
    } else {
        __nv_bfloat16* Chp = Ch + zo * sC;
        __nv_bfloat16* Clp = Cl + zo * sC;
        #pragma unroll
        for (int mi = 0; mi < 2; mi++)
            #pragma unroll
            for (int ni = 0; ni < 8; ni++) {
                int r = row0 + m0 + mi * 16 + er;
                int c = col0 + n0 + ni * 8 + ec;
                __nv_bfloat16 h0,h1,h2,h3,l0,l1,l2,l3;
                split1(acc[mi][ni][0] * alpha, h0, l0);
                split1(acc[mi][ni][1] * alpha, h1, l1);
                split1(acc[mi][ni][2] * alpha, h2, l2);
                split1(acc[mi][ni][3] * alpha, h3, l3);
                *(uint32_t*)&Chp[(long long)r * ldc + c]       = pack2(h0, h1);
                *(uint32_t*)&Clp[(long long)r * ldc + c]       = pack2(l0, l1);
                *(uint32_t*)&Chp[(long long)(r + 8) * ldc + c] = pack2(h2, h3);
                *(uint32_t*)&Clp[(long long)(r + 8) * ldc + c] = pack2(l2, l3);
            }
    }
}

// ---------------------------------------------------------------------------
// Causal row softmax: S fp32 -> split bf16 P (hi, lo). Zero fill to kmax.
// ---------------------------------------------------------------------------
__global__ __launch_bounds__(256) void softmax_split(
    const float* __restrict__ S, __nv_bfloat16* __restrict__ Ph,
    __nv_bfloat16* __restrict__ Pl, int T)
{
    const int q = blockIdx.x;
    const long long off = ((long long)blockIdx.y * T + q) * (long long)T;
    const float* row = S + off;

    __shared__ float buf[SEQ];
    __shared__ float red[8];

    const int t = threadIdx.x;
    const int n = q + 1;
    const int kmax = (q & ~(TM - 1)) + TM;

    float lmax = -3.0e38f;
    for (int i = t; i < n; i += 256) {
        float v = row[i];
        buf[i] = v;
        lmax = fmaxf(lmax, v);
    }
    #pragma unroll
    for (int o = 16; o; o >>= 1) lmax = fmaxf(lmax, __shfl_xor_sync(0xFFFFFFFFu, lmax, o));
    if ((t & 31) == 0) red[t >> 5] = lmax;
    __syncthreads();
    if (t < 32) {
        float v = (t < 8) ? red[t] : -3.0e38f;
        #pragma unroll
        for (int o = 4; o; o >>= 1) v = fmaxf(v, __shfl_xor_sync(0xFFFFFFFFu, v, o));
        if (t == 0) red[0] = v;
    }
    __syncthreads();
    const float gmax = red[0];

    float lsum = 0.f;
    for (int i = t; i < n; i += 256) {
        float e = expf(buf[i] - gmax);
        buf[i] = e;
        lsum += e;
    }
    __syncthreads();
    #pragma unroll
    for (int o = 16; o; o >>= 1) lsum += __shfl_xor_sync(0xFFFFFFFFu, lsum, o);
    if ((t & 31) == 0) red[t >> 5] = lsum;
    __syncthreads();
    if (t < 32) {
        float v = (t < 8) ? red[t] : 0.f;
        #pragma unroll
        for (int o = 4; o; o >>= 1) v += __shfl_xor_sync(0xFFFFFFFFu, v, o);
        if (t == 0) red[0] = v;
    }
    __syncthreads();
    const float inv = 1.f / red[0];

    for (int i = t; i < kmax; i += 256) {
        float v = (i < n) ? buf[i] * inv : 0.f;
        __nv_bfloat16 h, l;
        split1(v, h, l);
        Ph[off + i] = h;
        Pl[off + i] = l;
    }
}

// ---------------------------------------------------------------------------
extern "C" void kernel_launch(void* const* d_in, const int* in_sizes, int n_in,
                              void* d_out, int out_size)
{
    (void)in_sizes; (void)n_in; (void)out_size;
    const float* x  = (const float*)d_in[0];
    const float* Wq = (const float*)d_in[1];
    const float* Wk = (const float*)d_in[2];
    const float* Wv = (const float*)d_in[3];
    float* out = (float*)d_out;

    __nv_bfloat16 *xh,*xl,*wqh,*wql,*wkh,*wkl,*wvh,*wvl,*qh,*ql,*kh,*kl,*vth,*vtl,*ph,*pl;
    float* s;
    cudaGetSymbolAddress((void**)&xh,  g_xh);  cudaGetSymbolAddress((void**)&xl,  g_xl);
    cudaGetSymbolAddress((void**)&wqh, g_wqh); cudaGetSymbolAddress((void**)&wql, g_wql);
    cudaGetSymbolAddress((void**)&wkh, g_wkh); cudaGetSymbolAddress((void**)&wkl, g_wkl);
    cudaGetSymbolAddress((void**)&wvh, g_wvh); cudaGetSymbolAddress((void**)&wvl, g_wvl);
    cudaGetSymbolAddress((void**)&qh,  g_qh);  cudaGetSymbolAddress((void**)&ql,  g_ql);
    cudaGetSymbolAddress((void**)&kh,  g_kh);  cudaGetSymbolAddress((void**)&kl,  g_kl);
    cudaGetSymbolAddress((void**)&vth, g_vth); cudaGetSymbolAddress((void**)&vtl, g_vtl);
    cudaGetSymbolAddress((void**)&ph,  g_ph);  cudaGetSymbolAddress((void**)&pl,  g_pl);
    cudaGetSymbolAddress((void**)&s,   g_S);

    cudaFuncSetAttribute(gemm_bf3, cudaFuncAttributeMaxDynamicSharedMemorySize, SMEM_BYTES);

    const int M = BATCH * SEQ;                          // 8192
    const long long qkS = (long long)SEQ * CH;
    const long long vtS = (long long)CH * SEQ;
    const long long sS  = (long long)SEQ * SEQ;
    const float scale = 1.0f / 32.0f;

    // 0) split inputs to bf16 hi/lo
    split_k<<<(M * CH / 4) / 256, 256>>>((const float4*)x, (uint2*)xh, (uint2*)xl, M * CH / 4);
    split_k<<<(CH * CH / 4) / 256, 256>>>((const float4*)Wq, (uint2*)wqh, (uint2*)wql, CH * CH / 4);
    split_k<<<(CH * CH / 4) / 256, 256>>>((const float4*)Wk, (uint2*)wkh, (uint2*)wkl, CH * CH / 4);
    split_k<<<(CH * CH / 4) / 256, 256>>>((const float4*)Wv, (uint2*)wvh, (uint2*)wvl, CH * CH / 4);

    dim3 blk(512);

    // 1) Q/K projections (NT): [8192,1024] = x @ W^T, split store. Q pre-scaled.
    dim3 g1(CH / TN, M / TM, 1);
    gemm_bf3<<<g1, blk, SMEM_BYTES>>>(xh, xl, wqh, wql, nullptr, qh, ql,
                                      CH, CH, CH, CH, scale, 0, 0, 0, 0, 0, 1);
    gemm_bf3<<<g1, blk, SMEM_BYTES>>>(xh, xl, wkh, wkl, nullptr, kh, kl,
                                      CH, CH, CH, CH, 1.f, 0, 0, 0, 0, 0, 1);

    // 1b) Vt = Wv @ x^T per batch (NT, A=Wv rows=c, B=x rows=t): Vt[b][c][t]
    dim3 gv(SEQ / TN, CH / TM, BATCH);
    gemm_bf3<<<gv, blk, SMEM_BYTES>>>(wvh, wvl, xh, xl, nullptr, vth, vtl,
                                      CH, CH, CH, SEQ, 1.f, 0, qkS, vtS, 0, 0, 1);

    // 2) S = (Q*scale) @ K^T per batch (causal tile skip)
    dim3 g2(SEQ / TN, SEQ / TM, BATCH);
    gemm_bf3<<<g2, blk, SMEM_BYTES>>>(qh, ql, kh, kl, s, nullptr, nullptr,
                                      CH, CH, CH, SEQ, 1.f, qkS, qkS, sS, 1, 0, 0);

    // 3) softmax -> split P
    softmax_split<<<dim3(SEQ, BATCH), 256>>>(s, ph, pl, SEQ);

    // 4) out = P @ (V^T)^T per batch (NT against Vt, causal k-bound)
    dim3 g3(CH / TN, SEQ / TM, BATCH);
    gemm_bf3<<<g3, blk, SMEM_BYTES>>>(ph, pl, vth, vtl, out, nullptr, nullptr,
                                      SEQ, SEQ, SEQ, CH, 1.f, sS, vtS, qkS, 0, 1, 0);
}

// round 6
// speedup vs baseline: 3.3711x; 1.0974x over previous
#include <cuda_runtime.h>
#include <cuda_bf16.h>
#include <cstdint>

// Shape fixed by dataset: B=4, T=2048, C=1024, fp32 in/out.
#define BATCH 4
#define SEQ   2048
#define CH    1024

#define TM 128
#define TN 256
#define BK 32          // K elems per chunk (bf16) = 64B rows
#define STAGES 4

#define STG_A_H 0
#define STG_A_L 8192
#define STG_B_H 16384
#define STG_B_L 32768
#define STG_BYTES 49152
#define SMEM_BYTES (STAGES * STG_BYTES)   // 192 KB

#define SWZ64(o) ((o) ^ ((((unsigned)(o)) >> 3) & 0x30u))

// ---------------- scratch (__device__ globals; no allocs allowed) -------------
__device__ __nv_bfloat16 g_xh[(size_t)BATCH*SEQ*CH], g_xl[(size_t)BATCH*SEQ*CH];
__device__ __nv_bfloat16 g_wqth[CH*CH], g_wqtl[CH*CH];   // Wq^T split
__device__ __nv_bfloat16 g_wkth[CH*CH], g_wktl[CH*CH];   // Wk^T split
__device__ __nv_bfloat16 g_wvh[CH*CH],  g_wvl[CH*CH];
__device__ __nv_bfloat16 g_gth[CH*CH],  g_gtl[CH*CH];    // Gt = scale*(Wk^T Wq) split
__device__ __nv_bfloat16 g_yh[(size_t)BATCH*SEQ*CH], g_yl[(size_t)BATCH*SEQ*CH];   // Y = x*G^T
__device__ __nv_bfloat16 g_vth[(size_t)BATCH*CH*SEQ], g_vtl[(size_t)BATCH*CH*SEQ]; // V^T [b][c][t]
__device__ float         g_S [(size_t)BATCH*SEQ*SEQ];
__device__ __nv_bfloat16 g_ph[(size_t)BATCH*SEQ*SEQ], g_pl[(size_t)BATCH*SEQ*SEQ];

// ---------------- helpers ----------------
__device__ __forceinline__ uint32_t smem_u32(const void* p){
    uint32_t a;
    asm("{ .reg .u64 t; cvta.to.shared.u64 t, %1; cvt.u32.u64 %0, t; }" : "=r"(a) : "l"(p));
    return a;
}
__device__ __forceinline__ void split1(float v, __nv_bfloat16& h, __nv_bfloat16& l){
    h = __float2bfloat16_rn(v);
    l = __float2bfloat16_rn(v - __bfloat162float(h));
}
__device__ __forceinline__ uint32_t pack2(__nv_bfloat16 a, __nv_bfloat16 b){
    __nv_bfloat162 p = __halves2bfloat162(a, b);
    return *(uint32_t*)&p;
}
__device__ __forceinline__ void ldsm4(uint32_t* r, uint32_t a){
    asm volatile("ldmatrix.sync.aligned.m8n8.x4.shared.b16 {%0,%1,%2,%3}, [%4];"
        : "=r"(r[0]),"=r"(r[1]),"=r"(r[2]),"=r"(r[3]) : "r"(a));
}
__device__ __forceinline__ void mma16816(float* c, const uint32_t* a, const uint32_t* b){
    asm volatile(
        "mma.sync.aligned.m16n8k16.row.col.f32.bf16.bf16.f32 "
        "{%0,%1,%2,%3}, {%4,%5,%6,%7}, {%8,%9}, {%0,%1,%2,%3};"
        : "+f"(c[0]), "+f"(c[1]), "+f"(c[2]), "+f"(c[3])
        : "r"(a[0]), "r"(a[1]), "r"(a[2]), "r"(a[3]), "r"(b[0]), "r"(b[1]));
}
#define CPA16(dst, src) \
    asm volatile("cp.async.cg.shared.global [%0], [%1], 16;" :: "r"(dst), "l"(src))
#define CP_COMMIT() asm volatile("cp.async.commit_group;" ::: "memory")
#define CP_WAIT2()  asm volatile("cp.async.wait_group 2;" ::: "memory")

// ---------------------------------------------------------------------------
// split fp32 -> (hi, lo) bf16
// ---------------------------------------------------------------------------
__global__ __launch_bounds__(256) void split_k(
    const float4* __restrict__ in, uint2* __restrict__ oh, uint2* __restrict__ ol, int n4)
{
    int i = blockIdx.x * 256 + threadIdx.x;
    if (i >= n4) return;
    float4 v = in[i];
    __nv_bfloat16 h0,h1,h2,h3,l0,l1,l2,l3;
    split1(v.x,h0,l0); split1(v.y,h1,l1); split1(v.z,h2,l2); split1(v.w,h3,l3);
    uint2 H, L;
    H.x = pack2(h0,h1); H.y = pack2(h2,h3);
    L.x = pack2(l0,l1); L.y = pack2(l2,l3);
    oh[i] = H; ol[i] = L;
}

// ---------------------------------------------------------------------------
// transpose + split: out[c][r] = split(in[r][c]), square n x n (n=1024)
// ---------------------------------------------------------------------------
__global__ __launch_bounds__(256) void transpose_split(
    const float* __restrict__ in, __nv_bfloat16* __restrict__ oh,
    __nv_bfloat16* __restrict__ ol, int n)
{
    __shared__ float tile[32][33];
    const int bx = blockIdx.x * 32, by = blockIdx.y * 32;
    const int tx = threadIdx.x & 31, ty = threadIdx.x >> 5;   // 32 x 8
    #pragma unroll
    for (int i = 0; i < 4; i++) {
        int r = ty + i * 8;
        tile[r][tx] = in[(long long)(by + r) * n + bx + tx];
    }
    __syncthreads();
    #pragma unroll
    for (int i = 0; i < 4; i++) {
        int r = ty + i * 8;
        float v = tile[tx][r];
        __nv_bfloat16 h, l; split1(v, h, l);
        long long o = (long long)(bx + r) * n + by + tx;
        oh[o] = h; ol[o] = l;
    }
}

// ---------------------------------------------------------------------------
// NT GEMM, bf16 3-split on tensor cores, 128x256 tile, 512 threads:
//   C[m,n] = alpha * sum_k (Ah+Al)[m,k]*(Bh+Bl)[n,k]   (ll term dropped)
// mode 0: C fp32.  mode 1: split bf16 -> (Ch, Cl).
// causal: skip tiles with col0 > row0+TM-1.  kbound: K clipped to row0+TM.
// ---------------------------------------------------------------------------
__global__ __launch_bounds__(512, 1) void gemm_bf3(
    const __nv_bfloat16* __restrict__ Ah, const __nv_bfloat16* __restrict__ Al,
    const __nv_bfloat16* __restrict__ Bh, const __nv_bfloat16* __restrict__ Bl,
    float* __restrict__ C, __nv_bfloat16* __restrict__ Ch, __nv_bfloat16* __restrict__ Cl,
    int K, int lda, int ldb, int ldc, float alpha,
    long long sA, long long sB, long long sC,
    int causal, int kbound, int mode)
{
    const int row0 = blockIdx.y * TM;
    const int col0 = blockIdx.x * TN;
    if (causal && col0 > row0 + (TM - 1)) return;

    const long long zo = blockIdx.z;
    Ah += zo * sA; Al += zo * sA;
    Bh += zo * sB; Bl += zo * sB;

    const int kend = kbound ? min(K, row0 + TM) : K;
    const int nch  = kend / BK;

    extern __shared__ char sm[];
    const uint32_t smu = smem_u32(sm);

    const int t = threadIdx.x;

    // ---- producer mapping: 1x16B per thread per 8KB region ----
    const int prow = t >> 2;               // 0..127
    const int pch  = t & 3;                // 16B chunk within 64B row
    const uint32_t dA = SWZ64((uint32_t)(prow * 64 + pch * 16));
    const __nv_bfloat16* gAh  = Ah + (long long)(row0 + prow) * lda + pch * 8;
    const __nv_bfloat16* gAl  = Al + (long long)(row0 + prow) * lda + pch * 8;
    const __nv_bfloat16* gBh0 = Bh + (long long)(col0 + prow) * ldb + pch * 8;
    const __nv_bfloat16* gBh1 = Bh + (long long)(col0 + prow + 128) * ldb + pch * 8;
    const __nv_bfloat16* gBl0 = Bl + (long long)(col0 + prow) * ldb + pch * 8;
    const __nv_bfloat16* gBl1 = Bl + (long long)(col0 + prow + 128) * ldb + pch * 8;

    #define LOAD_CHUNK(s, i) do {                                              \
        uint32_t base = smu + (uint32_t)(s) * STG_BYTES;                       \
        long long kk0 = (long long)(i) * BK;                                   \
        CPA16(base + STG_A_H + dA,        gAh  + kk0);                         \
        CPA16(base + STG_A_L + dA,        gAl  + kk0);                         \
        CPA16(base + STG_B_H + dA,        gBh0 + kk0);                         \
        CPA16(base + STG_B_H + dA + 8192, gBh1 + kk0);                         \
        CPA16(base + STG_B_L + dA,        gBl0 + kk0);                         \
        CPA16(base + STG_B_L + dA + 8192, gBl1 + kk0);                         \
        CP_COMMIT();                                                           \
    } while (0)

    // ---- consumer mapping: 16 warps, warp tile 32x64 (4x4 warp grid) ----
    const int wid  = t >> 5;
    const int lane = t & 31;
    const int m0 = (wid >> 2) * 32;
    const int n0 = (wid & 3) * 64;

    const int rr = lane & 7;
    const int t4 = lane >> 3;
    const int arow = m0 + rr + (t4 & 1) * 8;
    const uint32_t a_base = (uint32_t)(arow * 64 + (t4 >> 1) * 16);
    const uint32_t aswz   = (uint32_t)(((arow >> 1) & 3) << 4);
    const int brow = n0 + rr + (t4 >> 1) * 8;
    const uint32_t b_base = (uint32_t)(brow * 64 + (t4 & 1) * 16);
    const uint32_t bswz   = (uint32_t)(((brow >> 1) & 3) << 4);

    float acc[2][8][4];
    #pragma unroll
    for (int mi = 0; mi < 2; mi++)
        #pragma unroll
        for (int ni = 0; ni < 8; ni++)
            #pragma unroll
            for (int r = 0; r < 4; r++) acc[mi][ni][r] = 0.f;

    int fetch = 0;
    #pragma unroll
    for (int s = 0; s < STAGES - 1; s++) {
        if (fetch < nch) { LOAD_CHUNK(fetch % STAGES, fetch); fetch++; }
        else CP_COMMIT();
    }

    for (int i = 0; i < nch; i++) {
        CP_WAIT2();
        __syncthreads();

        if (fetch < nch) { LOAD_CHUNK(fetch % STAGES, fetch); fetch++; }
        else CP_COMMIT();

        const uint32_t sb = smu + (uint32_t)(i % STAGES) * STG_BYTES;
        #pragma unroll
        for (int ks = 0; ks < 2; ks++) {
            uint32_t ah[2][4], al[2][4];
            #pragma unroll
            for (int mi = 0; mi < 2; mi++) {
                uint32_t o = (a_base + mi * 1024 + ks * 32) ^ aswz;
                ldsm4(ah[mi], sb + STG_A_H + o);
                ldsm4(al[mi], sb + STG_A_L + o);
            }
            #pragma unroll
            for (int half = 0; half < 2; half++) {
                uint32_t bh[2][4], bl[2][4];
                #pragma unroll
                for (int p = 0; p < 2; p++) {
                    uint32_t o = (b_base + (half * 2 + p) * 1024 + ks * 32) ^ bswz;
                    ldsm4(bh[p], sb + STG_B_H + o);
                    ldsm4(bl[p], sb + STG_B_L + o);
                }
                #pragma unroll
                for (int mi = 0; mi < 2; mi++)
                    #pragma unroll
                    for (int p = 0; p < 2; p++)
                        #pragma unroll
                        for (int sub = 0; sub < 2; sub++) {
                            int ni = half * 4 + p * 2 + sub;
                            mma16816(acc[mi][ni], ah[mi], bh[p] + 2 * sub);
                            mma16816(acc[mi][ni], al[mi], bh[p] + 2 * sub);
                            mma16816(acc[mi][ni], ah[mi], bl[p] + 2 * sub);
                        }
            }
        }
    }

    // -------- epilogue --------
    const int er = lane >> 2;
    const int ec = (lane & 3) * 2;

    if (mode == 0) {
        float* Cp = C + zo * sC;
        #pragma unroll
        for (int mi = 0; mi < 2; mi++)
            #pragma unroll
            for (int ni = 0; ni < 8; ni++) {
                int r = row0 + m0 + mi * 16 + er;
                int c = col0 + n0 + ni * 8 + ec;
                float2 v0 = make_float2(acc[mi][ni][0] * alpha, acc[mi][ni][1] * alpha);
                float2 v1 = make_float2(acc[mi][ni][2] * alpha, acc[mi][ni][3] * alpha);
                *(float2*)&Cp[(long long)r * ldc + c]       = v0;
                *(float2*)&Cp[(long long)(r + 8) * ldc + c] = v1;
            }
    } else {
        __nv_bfloat16* Chp = Ch + zo * sC;
        __nv_bfloat16* Clp = Cl + zo * sC;
        #pragma unroll
        for (int mi = 0; mi < 2; mi++)
            #pragma unroll
            for (int ni = 0; ni < 8; ni++) {
                int r = row0 + m0 + mi * 16 + er;
                int c = col0 + n0 + ni * 8 + ec;
                __nv_bfloat16 h0,h1,h2,h3,l0,l1,l2,l3;
                split1(acc[mi][ni][0] * alpha, h0, l0);
                split1(acc[mi][ni][1] * alpha, h1, l1);
                split1(acc[mi][ni][2] * alpha, h2, l2);
                split1(acc[mi][ni][3] * alpha, h3, l3);
                *(uint32_t*)&Chp[(long long)r * ldc + c]       = pack2(h0, h1);
                *(uint32_t*)&Clp[(long long)r * ldc + c]       = pack2(l0, l1);
                *(uint32_t*)&Chp[(long long)(r + 8) * ldc + c] = pack2(h2, h3);
                *(uint32_t*)&Clp[(long long)(r + 8) * ldc + c] = pack2(l2, l3);
            }
    }
}

// ---------------------------------------------------------------------------
// Causal row softmax: S fp32 -> split bf16 P (hi, lo). Zero fill to kmax.
// ---------------------------------------------------------------------------
__global__ __launch_bounds__(256) void softmax_split(
    const float* __restrict__ S, __nv_bfloat16* __restrict__ Ph,
    __nv_bfloat16* __restrict__ Pl, int T)
{
    const int q = blockIdx.x;
    const long long off = ((long long)blockIdx.y * T + q) * (long long)T;
    const float* row = S + off;

    __shared__ float buf[SEQ];
    __shared__ float red[8];

    const int t = threadIdx.x;
    const int n = q + 1;
    const int kmax = (q & ~(TM - 1)) + TM;

    float lmax = -3.0e38f;
    for (int i = t; i < n; i += 256) {
        float v = row[i];
        buf[i] = v;
        lmax = fmaxf(lmax, v);
    }
    #pragma unroll
    for (int o = 16; o; o >>= 1) lmax = fmaxf(lmax, __shfl_xor_sync(0xFFFFFFFFu, lmax, o));
    if ((t & 31) == 0) red[t >> 5] = lmax;
    __syncthreads();
    if (t < 32) {
        float v = (t < 8) ? red[t] : -3.0e38f;
        #pragma unroll
        for (int o = 4; o; o >>= 1) v = fmaxf(v, __shfl_xor_sync(0xFFFFFFFFu, v, o));
        if (t == 0) red[0] = v;
    }
    __syncthreads();
    const float gmax = red[0];

    float lsum = 0.f;
    for (int i = t; i < n; i += 256) {
        float e = expf(buf[i] - gmax);
        buf[i] = e;
        lsum += e;
    }
    __syncthreads();
    #pragma unroll
    for (int o = 16; o; o >>= 1) lsum += __shfl_xor_sync(0xFFFFFFFFu, lsum, o);
    if ((t & 31) == 0) red[t >> 5] = lsum;
    __syncthreads();
    if (t < 32) {
        float v = (t < 8) ? red[t] : 0.f;
        #pragma unroll
        for (int o = 4; o; o >>= 1) v += __shfl_xor_sync(0xFFFFFFFFu, v, o);
        if (t == 0) red[0] = v;
    }
    __syncthreads();
    const float inv = 1.f / red[0];

    for (int i = t; i < kmax; i += 256) {
        float v = (i < n) ? buf[i] * inv : 0.f;
        __nv_bfloat16 h, l;
        split1(v, h, l);
        Ph[off + i] = h;
        Pl[off + i] = l;
    }
}

// ---------------------------------------------------------------------------
extern "C" void kernel_launch(void* const* d_in, const int* in_sizes, int n_in,
                              void* d_out, int out_size)
{
    (void)in_sizes; (void)n_in; (void)out_size;
    const float* x  = (const float*)d_in[0];
    const float* Wq = (const float*)d_in[1];
    const float* Wk = (const float*)d_in[2];
    const float* Wv = (const float*)d_in[3];
    float* out = (float*)d_out;

    __nv_bfloat16 *xh,*xl,*wqth,*wqtl,*wkth,*wktl,*wvh,*wvl,*gth,*gtl;
    __nv_bfloat16 *yh,*yl,*vth,*vtl,*ph,*pl;
    float* s;
    cudaGetSymbolAddress((void**)&xh,   g_xh);   cudaGetSymbolAddress((void**)&xl,   g_xl);
    cudaGetSymbolAddress((void**)&wqth, g_wqth); cudaGetSymbolAddress((void**)&wqtl, g_wqtl);
    cudaGetSymbolAddress((void**)&wkth, g_wkth); cudaGetSymbolAddress((void**)&wktl, g_wktl);
    cudaGetSymbolAddress((void**)&wvh,  g_wvh);  cudaGetSymbolAddress((void**)&wvl,  g_wvl);
    cudaGetSymbolAddress((void**)&gth,  g_gth);  cudaGetSymbolAddress((void**)&gtl,  g_gtl);
    cudaGetSymbolAddress((void**)&yh,   g_yh);   cudaGetSymbolAddress((void**)&yl,   g_yl);
    cudaGetSymbolAddress((void**)&vth,  g_vth);  cudaGetSymbolAddress((void**)&vtl,  g_vtl);
    cudaGetSymbolAddress((void**)&ph,   g_ph);   cudaGetSymbolAddress((void**)&pl,   g_pl);
    cudaGetSymbolAddress((void**)&s,    g_S);

    cudaFuncSetAttribute(gemm_bf3, cudaFuncAttributeMaxDynamicSharedMemorySize, SMEM_BYTES);

    const int M = BATCH * SEQ;                          // 8192
    const long long qkS = (long long)SEQ * CH;
    const long long vtS = (long long)CH * SEQ;
    const long long sS  = (long long)SEQ * SEQ;
    const float scale = 1.0f / 32.0f;                   // C^-0.5

    // 0) prepare operands
    split_k<<<(M * CH / 4) / 256, 256>>>((const float4*)x, (uint2*)xh, (uint2*)xl, M * CH / 4);
    split_k<<<(CH * CH / 4) / 256, 256>>>((const float4*)Wv, (uint2*)wvh, (uint2*)wvl, CH * CH / 4);
    transpose_split<<<dim3(32, 32), 256>>>(Wq, wqth, wqtl, CH);
    transpose_split<<<dim3(32, 32), 256>>>(Wk, wkth, wktl, CH);

    dim3 blk(512);

    // 1) Gt = scale * Wk^T @ Wq (NT on transposed weights), split out
    dim3 gg(CH / TN, CH / TM, 1);
    gemm_bf3<<<gg, blk, SMEM_BYTES>>>(wkth, wktl, wqth, wqtl, nullptr, gth, gtl,
                                      CH, CH, CH, CH, scale, 0, 0, 0, 0, 0, 1);

    // 2) Y = x @ Gt^T (NT), split out   [8192, 1024]
    dim3 gy(CH / TN, M / TM, 1);
    gemm_bf3<<<gy, blk, SMEM_BYTES>>>(xh, xl, gth, gtl, nullptr, yh, yl,
                                      CH, CH, CH, CH, 1.f, 0, 0, 0, 0, 0, 1);

    // 3) Vt = Wv @ x^T per batch (NT): Vt[b][c][t], split out
    dim3 gv(SEQ / TN, CH / TM, BATCH);
    gemm_bf3<<<gv, blk, SMEM_BYTES>>>(wvh, wvl, xh, xl, nullptr, vth, vtl,
                                      CH, CH, CH, SEQ, 1.f, 0, qkS, vtS, 0, 0, 1);

    // 4) S = Y @ x^T per batch (NT, causal tile skip) -> fp32
    dim3 g2(SEQ / TN, SEQ / TM, BATCH);
    gemm_bf3<<<g2, blk, SMEM_BYTES>>>(yh, yl, xh, xl, s, nullptr, nullptr,
                                      CH, CH, CH, SEQ, 1.f, qkS, qkS, sS, 1, 0, 0);

    // 5) softmax -> split P
    softmax_split<<<dim3(SEQ, BATCH), 256>>>(s, ph, pl, SEQ);

    // 6) out = P @ (V^T)^T per batch (NT against Vt, causal k-bound)
    dim3 g3(CH / TN, SEQ / TM, BATCH);
    gemm_bf3<<<g3, blk, SMEM_BYTES>>>(ph, pl, vth, vtl, out, nullptr, nullptr,
                                      SEQ, SEQ, SEQ, CH, 1.f, sS, vtS, qkS, 0, 1, 0);
}